// round 6
// baseline (speedup 1.0000x reference)
#include <cuda_runtime.h>

// Problem constants (fixed shapes for this problem instance)
constexpr int N_   = 2048;   // nodes
constexpr int F_   = 512;    // features
constexpr int F4   = F_ / 4; // float4 groups per row (128)
constexpr int M_   = 10;     // chebyshev order
constexpr int Q_   = 64;     // quadrature points
constexpr int ELL  = 64;     // max nnz per row of L_hat (expected ~16, 12-sigma safe)
constexpr float TAIL_TOL = 1e-7f;   // drop tolerance for trailing Chebyshev terms

// Scratch: __device__ globals (sanctioned; no cudaMalloc allowed)
__device__ float g_cT[(M_ + 1) * N_];   // transposed coefficients cT[k*N + row]
__device__ int   g_cmax[M_ + 1];        // per-k max |c| as float bits (atomicMax, idempotent)
__device__ float g_LvalT[ELL * N_];     // transposed ELL values  [tnz*N + row]
__device__ int   g_LcolT[ELL * N_];     // transposed ELL columns [tnz*N + row]
__device__ int   g_Lcnt[N_];            // nnz per row

// ---------------------------------------------------------------------------
// Kernel 1: per-node Chebyshev-Gauss quadrature coefficients c[i, 0..M],
// stored transposed; also reduces per-k max|c| (k>=2) via atomicMax on the
// non-negative float bit pattern (monotone -> idempotent across graph replays).
// ---------------------------------------------------------------------------
__global__ void k_coeff(const float* __restrict__ t, const float* __restrict__ eigmax) {
    int i = blockIdx.x * blockDim.x + threadIdx.x;
    if (i >= N_) return;
    float s  = expf(t[i]);
    float em = eigmax[0];
    float acc[M_ + 1];
#pragma unroll
    for (int k = 0; k <= M_; k++) acc[k] = 0.0f;

    const float PI = 3.14159265358979323846f;
    for (int q = 0; q < Q_; q++) {
        float theta = PI * ((float)q + 0.5f) / (float)Q_;
        float ct    = cosf(theta);
        float lam   = em * 0.5f * (ct + 1.0f);
        float w     = expf(-s * lam);
        float ckm1 = 1.0f;
        float ck   = ct;
        acc[0] += w;
        acc[1] += w * ck;
#pragma unroll
        for (int k = 2; k <= M_; k++) {
            float cn = 2.0f * ct * ck - ckm1;
            ckm1 = ck; ck = cn;
            acc[k] += w * cn;
        }
    }
    float scale = 2.0f / (float)Q_;
    float vloc[M_ + 1];
#pragma unroll
    for (int k = 0; k <= M_; k++) {
        float v = scale * acc[k];
        if (k == 0) v *= 0.5f;
        vloc[k] = v;
        g_cT[k * N_ + i] = v;
    }
    // warp-reduce max |c[k]| then one atomic per warp per k
#pragma unroll
    for (int k = 2; k <= M_; k++) {
        float m = fabsf(vloc[k]);
#pragma unroll
        for (int o = 16; o > 0; o >>= 1)
            m = fmaxf(m, __shfl_xor_sync(0xffffffffu, m, o));
        if ((threadIdx.x & 31) == 0)
            atomicMax(&g_cmax[k], __float_as_int(m));
    }
}

// ---------------------------------------------------------------------------
// Kernel 2: extract sparse ELL of L_hat = (2/eigmax)*P_n - I, stored
// TRANSPOSED (g_LvalT[tnz*N + row]) so the main kernel's per-lane row access
// is coalesced. One warp per row; float4 loads; ballot-ordered compaction.
// ---------------------------------------------------------------------------
__global__ void k_build(const float* __restrict__ P, const float* __restrict__ eigmax) {
    int warps_per_blk = blockDim.x >> 5;
    int row  = blockIdx.x * warps_per_blk + (threadIdx.x >> 5);
    int lane = threadIdx.x & 31;
    if (row >= N_) return;
    float sc = 2.0f / eigmax[0];
    int cnt = 0;
    for (int base = 0; base < N_; base += 128) {
        int col0 = base + lane * 4;
        float4 p = *reinterpret_cast<const float4*>(&P[(size_t)row * N_ + col0]);
        float pv[4] = {p.x, p.y, p.z, p.w};
#pragma unroll
        for (int e = 0; e < 4; e++) {
            int col = col0 + e;
            float v = sc * pv[e] - (col == row ? 1.0f : 0.0f);
            unsigned m = __ballot_sync(0xffffffffu, v != 0.0f);
            if (v != 0.0f) {
                int pos = cnt + __popc(m & ((1u << lane) - 1u));
                if (pos < ELL) {
                    g_LvalT[pos * N_ + row] = v;
                    g_LcolT[pos * N_ + row] = col;
                }
            }
            cnt += __popc(m);
        }
    }
    if (lane == 0) g_Lcnt[row] = cnt < ELL ? cnt : ELL;
}

// ---------------------------------------------------------------------------
// Kernel 3: the ENTIRE Chebyshev recurrence + output, fused.
// One block per float4 feature column (128 blocks, 512 threads).
// All three y_k buffers live in shared memory (3 x 2048 x 16B = 96 KB);
// the output accumulator lives in registers. Only block-level syncs.
//   y0 = x ; y1 = L@y0 ; y_k = 2 L@y_{k-1} - y_{k-2}
//   out = sum_k c[:,k] * y_k     (k up to adaptive kmax, TAIL_TOL criterion)
// ---------------------------------------------------------------------------
__global__ void __launch_bounds__(512) k_main(const float* __restrict__ x,
                                              float* __restrict__ out,
                                              const float* __restrict__ t,
                                              int do_tail) {
    extern __shared__ float4 sm[];
    float4* yb0 = sm;
    float4* yb1 = sm + N_;
    float4* yb2 = sm + 2 * N_;

    int c4  = blockIdx.x;     // feature float4 column
    int tid = threadIdx.x;
    const float4* X4 = reinterpret_cast<const float4*>(x);
    float4* O4 = reinterpret_cast<float4*>(out);

    int   cnt[4];
    float4 oacc[4];

    // Phase A: load x column slice -> y0, start out accumulation with c0
#pragma unroll
    for (int i = 0; i < 4; i++) {
        int r = tid + i * 512;
        float4 xv = X4[(size_t)r * F4 + c4];
        yb0[r] = xv;
        float c0 = g_cT[r];          // k = 0
        oacc[i] = make_float4(c0 * xv.x, c0 * xv.y, c0 * xv.z, c0 * xv.w);
        cnt[i] = g_Lcnt[r];
    }
    __syncthreads();

    int cm = max(max(cnt[0], cnt[1]), max(cnt[2], cnt[3]));

    // k = 1: y1 = L @ y0
    {
        float4 acc[4];
#pragma unroll
        for (int i = 0; i < 4; i++) acc[i] = make_float4(0.f, 0.f, 0.f, 0.f);
        for (int tnz = 0; tnz < cm; tnz++) {
#pragma unroll
            for (int i = 0; i < 4; i++) {
                if (tnz < cnt[i]) {
                    int r = tid + i * 512;
                    float v = g_LvalT[tnz * N_ + r];
                    int   j = g_LcolT[tnz * N_ + r];
                    float4 b = yb0[j];
                    acc[i].x = fmaf(v, b.x, acc[i].x);
                    acc[i].y = fmaf(v, b.y, acc[i].y);
                    acc[i].z = fmaf(v, b.z, acc[i].z);
                    acc[i].w = fmaf(v, b.w, acc[i].w);
                }
            }
        }
#pragma unroll
        for (int i = 0; i < 4; i++) {
            int r = tid + i * 512;
            yb1[r] = acc[i];
            float c1 = g_cT[N_ + r];
            oacc[i].x = fmaf(c1, acc[i].x, oacc[i].x);
            oacc[i].y = fmaf(c1, acc[i].y, oacc[i].y);
            oacc[i].z = fmaf(c1, acc[i].z, oacc[i].z);
            oacc[i].w = fmaf(c1, acc[i].w, oacc[i].w);
        }
    }
    __syncthreads();

    // adaptive kmax: largest k whose suffix-sum of max|c| exceeds TAIL_TOL
    int kmax = 1;
    {
        float tail = 0.0f;
        for (int k = M_; k >= 2; k--) {
            tail += __int_as_float(g_cmax[k]);
            if (tail > TAIL_TOL) { kmax = k; break; }
        }
    }

    float4 *yp = yb0, *yc = yb1, *yn = yb2;
    for (int k = 2; k <= kmax; k++) {
        float4 acc[4];
#pragma unroll
        for (int i = 0; i < 4; i++) acc[i] = make_float4(0.f, 0.f, 0.f, 0.f);
        for (int tnz = 0; tnz < cm; tnz++) {
#pragma unroll
            for (int i = 0; i < 4; i++) {
                if (tnz < cnt[i]) {
                    int r = tid + i * 512;
                    float v = g_LvalT[tnz * N_ + r];
                    int   j = g_LcolT[tnz * N_ + r];
                    float4 b = yc[j];
                    acc[i].x = fmaf(v, b.x, acc[i].x);
                    acc[i].y = fmaf(v, b.y, acc[i].y);
                    acc[i].z = fmaf(v, b.z, acc[i].z);
                    acc[i].w = fmaf(v, b.w, acc[i].w);
                }
            }
        }
        const float* cT = &g_cT[k * N_];
#pragma unroll
        for (int i = 0; i < 4; i++) {
            int r = tid + i * 512;
            float4 p = yp[r];
            float4 ynv = make_float4(2.0f * acc[i].x - p.x, 2.0f * acc[i].y - p.y,
                                     2.0f * acc[i].z - p.z, 2.0f * acc[i].w - p.w);
            yn[r] = ynv;
            float ck = cT[r];
            oacc[i].x = fmaf(ck, ynv.x, oacc[i].x);
            oacc[i].y = fmaf(ck, ynv.y, oacc[i].y);
            oacc[i].z = fmaf(ck, ynv.z, oacc[i].z);
            oacc[i].w = fmaf(ck, ynv.w, oacc[i].w);
        }
        __syncthreads();
        float4* tmp = yp; yp = yc; yc = yn; yn = tmp;
    }

    // write output
#pragma unroll
    for (int i = 0; i < 4; i++) {
        int r = tid + i * 512;
        O4[(size_t)r * F4 + c4] = oacc[i];
    }

    // second reference output is t -> tail of d_out (block 0 only)
    if (do_tail && blockIdx.x == 0) {
        for (int j = tid; j < N_; j += 512)
            out[(size_t)N_ * F_ + j] = t[j];
    }
}

// ---------------------------------------------------------------------------
extern "C" void kernel_launch(void* const* d_in, const int* in_sizes, int n_in,
                              void* d_out, int out_size) {
    const float* x   = (const float*)d_in[0];   // [N, F]
    const float* P   = (const float*)d_in[1];   // [N, N]
    const float* t   = (const float*)d_in[2];   // [N]
    const float* eig = (const float*)d_in[3];   // [1]
    float* out = (float*)d_out;

    constexpr size_t SMEM = 3ull * N_ * sizeof(float4);   // 96 KB
    static bool attr_set = false;
    if (!attr_set) {
        cudaFuncSetAttribute(k_main, cudaFuncAttributeMaxDynamicSharedMemorySize,
                             (int)SMEM);
        attr_set = true;
    }

    k_coeff<<<(N_ + 255) / 256, 256>>>(t, eig);
    k_build<<<N_ / 8, 256>>>(P, eig);            // 8 warps/block, 1 warp/row

    int do_tail = (out_size >= N_ * F_ + N_) ? 1 : 0;
    k_main<<<F4, 512, SMEM>>>(x, out, t, do_tail);
}

// round 7
// speedup vs baseline: 2.2390x; 2.2390x over previous
#include <cuda_runtime.h>

// Problem constants (fixed shapes for this problem instance)
constexpr int N_   = 2048;   // nodes
constexpr int F_   = 512;    // features
constexpr int F4   = F_ / 4; // float4 groups per row (128)
constexpr int M_   = 10;     // chebyshev order
constexpr int Q_   = 64;     // quadrature points
constexpr int ELL  = 64;     // max nnz per row of L_hat (expected ~16, 12-sigma safe)
constexpr float TAIL_TOL = 1e-7f;   // drop tolerance for trailing Chebyshev terms

// Scratch: __device__ globals (sanctioned; no cudaMalloc allowed)
__device__ float g_Y[3][N_ * F_];       // ping-pong Chebyshev y_k buffers (3 x 4 MB)
__device__ float g_cT[(M_ + 1) * N_];   // transposed coefficients cT[k*N + row]
__device__ int   g_cmax[M_ + 1];        // per-k max |c| as float bits (atomicMax, idempotent)
__device__ float g_Lval[N_ * ELL];      // ELL sparse L_hat values (row-major)
__device__ int   g_Lcol[N_ * ELL];      // ELL sparse L_hat column indices
__device__ int   g_Lcnt[N_];            // nnz per row

// ---------------------------------------------------------------------------
// Kernel 1 (fused prep): blocks [0,256) build the ELL sparse L_hat; blocks
// [256,512) compute per-node Chebyshev-Gauss coefficients (one warp/node,
// lanes split the Q=64 quadrature points) + per-k max|c| via atomicMax on
// positive float bits (monotone -> idempotent across graph replays).
// ---------------------------------------------------------------------------
__global__ void __launch_bounds__(256) k_prep(const float* __restrict__ P,
                                              const float* __restrict__ t,
                                              const float* __restrict__ eigmax) {
    int warp = threadIdx.x >> 5;
    int lane = threadIdx.x & 31;

    if (blockIdx.x < 256) {
        // ---- build: one warp per row, float4 loads, ballot compaction ----
        int row = blockIdx.x * 8 + warp;
        float sc = 2.0f / eigmax[0];
        int cnt = 0;
        for (int base = 0; base < N_; base += 128) {
            int col0 = base + lane * 4;
            float4 p = *reinterpret_cast<const float4*>(&P[(size_t)row * N_ + col0]);
            float pv[4] = {p.x, p.y, p.z, p.w};
#pragma unroll
            for (int e = 0; e < 4; e++) {
                int col = col0 + e;
                float v = sc * pv[e] - (col == row ? 1.0f : 0.0f);
                unsigned m = __ballot_sync(0xffffffffu, v != 0.0f);
                if (v != 0.0f) {
                    int pos = cnt + __popc(m & ((1u << lane) - 1u));
                    if (pos < ELL) {
                        g_Lval[row * ELL + pos] = v;
                        g_Lcol[row * ELL + pos] = col;
                    }
                }
                cnt += __popc(m);
            }
        }
        if (lane == 0) g_Lcnt[row] = cnt < ELL ? cnt : ELL;
    } else {
        // ---- coeff: one warp per node, lanes over quadrature points ----
        int node = (blockIdx.x - 256) * 8 + warp;
        float s  = expf(t[node]);
        float em = eigmax[0];
        float a[M_ + 1];
#pragma unroll
        for (int k = 0; k <= M_; k++) a[k] = 0.0f;

        const float PI = 3.14159265358979323846f;
#pragma unroll
        for (int h = 0; h < 2; h++) {
            int q = lane + h * 32;
            float theta = PI * ((float)q + 0.5f) / (float)Q_;
            float ct    = cosf(theta);
            float lam   = em * 0.5f * (ct + 1.0f);
            float w     = expf(-s * lam);
            float ckm1 = 1.0f;
            float ck   = ct;
            a[0] += w;
            a[1] += w * ck;
#pragma unroll
            for (int k = 2; k <= M_; k++) {
                float cn = 2.0f * ct * ck - ckm1;
                ckm1 = ck; ck = cn;
                a[k] += w * cn;
            }
        }
        // lane reduction
#pragma unroll
        for (int k = 0; k <= M_; k++) {
#pragma unroll
            for (int o = 16; o > 0; o >>= 1)
                a[k] += __shfl_xor_sync(0xffffffffu, a[k], o);
        }
        if (lane == 0) {
            float scale = 2.0f / (float)Q_;
#pragma unroll
            for (int k = 0; k <= M_; k++) {
                float v = scale * a[k];
                if (k == 0) v *= 0.5f;
                g_cT[k * N_ + node] = v;
                if (k >= 2) atomicMax(&g_cmax[k], __float_as_int(fabsf(v)));
            }
        }
    }
}

// ---------------------------------------------------------------------------
// Kernel 2: first recurrence level.  y1 = L_hat @ x ; out = c0*x + c1*y1.
// 256 threads = 2 rows per block (1024 blocks). Also writes the t-tail.
// ---------------------------------------------------------------------------
__global__ void __launch_bounds__(256) k_first(const float* __restrict__ x,
                                               float* __restrict__ out,
                                               const float* __restrict__ t,
                                               int do_tail) {
    int sub = threadIdx.x >> 7;        // 0..1 row within block
    int c4  = threadIdx.x & 127;       // feature float4 group
    int row = blockIdx.x * 2 + sub;

    __shared__ float sval[2][ELL];
    __shared__ int   scol[2][ELL];
    if (threadIdx.x < 2 * ELL) {
        int s2 = threadIdx.x >> 6, ix = threadIdx.x & 63;
        int r2 = blockIdx.x * 2 + s2;
        sval[s2][ix] = g_Lval[r2 * ELL + ix];
        scol[s2][ix] = g_Lcol[r2 * ELL + ix];
    }
    __syncthreads();

    int cnt = g_Lcnt[row];
    const float4* X4 = reinterpret_cast<const float4*>(x);
    int o = row * F4 + c4;
    float4 xv = X4[o];

    float4 acc = make_float4(0.f, 0.f, 0.f, 0.f);
#pragma unroll 8
    for (int tnz = 0; tnz < cnt; tnz++) {
        float v = sval[sub][tnz];
        int   j = scol[sub][tnz];
        float4 b = __ldg(&X4[j * F4 + c4]);
        acc.x = fmaf(v, b.x, acc.x);
        acc.y = fmaf(v, b.y, acc.y);
        acc.z = fmaf(v, b.z, acc.z);
        acc.w = fmaf(v, b.w, acc.w);
    }

    reinterpret_cast<float4*>(g_Y[0])[o] = acc;   // y1
    float c0 = g_cT[row];
    float c1 = g_cT[N_ + row];
    float4 ov = make_float4(fmaf(c1, acc.x, c0 * xv.x),
                            fmaf(c1, acc.y, c0 * xv.y),
                            fmaf(c1, acc.z, c0 * xv.z),
                            fmaf(c1, acc.w, c0 * xv.w));
    reinterpret_cast<float4*>(out)[o] = ov;

    if (do_tail && blockIdx.x == 0) {
        for (int i = threadIdx.x; i < N_; i += 256)
            out[(size_t)N_ * F_ + i] = t[i];
    }
}

// ---------------------------------------------------------------------------
// Kernel 3: one Chebyshev recurrence step.
//   y_new = 2 * L_hat @ y_cur - y_prev ; out += c[:,k] * y_new
// ip == -1 means y_prev = x (k == 2, avoids materializing y0).
// Early-exits when the suffix-sum of max|c| over j>=k is below TAIL_TOL.
// ---------------------------------------------------------------------------
__global__ void __launch_bounds__(256) k_step(const float* __restrict__ x,
                                              int ip, int ic, int inew, int k,
                                              float* __restrict__ out) {
    float tail = 0.0f;
#pragma unroll
    for (int kk = M_; kk >= 2; kk--)
        if (kk >= k) tail += __int_as_float(g_cmax[kk]);
    if (tail <= TAIL_TOL) return;

    const float4* Yprev = (ip < 0) ? reinterpret_cast<const float4*>(x)
                                   : reinterpret_cast<const float4*>(g_Y[ip]);
    const float4* Ycur  = reinterpret_cast<const float4*>(g_Y[ic]);
    float4*       Ynew  = reinterpret_cast<float4*>(g_Y[inew]);

    int sub = threadIdx.x >> 7;
    int c4  = threadIdx.x & 127;
    int row = blockIdx.x * 2 + sub;

    __shared__ float sval[2][ELL];
    __shared__ int   scol[2][ELL];
    if (threadIdx.x < 2 * ELL) {
        int s2 = threadIdx.x >> 6, ix = threadIdx.x & 63;
        int r2 = blockIdx.x * 2 + s2;
        sval[s2][ix] = g_Lval[r2 * ELL + ix];
        scol[s2][ix] = g_Lcol[r2 * ELL + ix];
    }
    __syncthreads();

    int cnt = g_Lcnt[row];
    float ck = g_cT[k * N_ + row];
    int o = row * F4 + c4;

    // hoist independent loads to overlap with the gather loop's L2 latency
    float4 p  = Yprev[o];
    float4 ov = reinterpret_cast<float4*>(out)[o];

    float4 acc = make_float4(0.f, 0.f, 0.f, 0.f);
#pragma unroll 8
    for (int tnz = 0; tnz < cnt; tnz++) {
        float v = sval[sub][tnz];
        int   j = scol[sub][tnz];
        float4 b = __ldg(&Ycur[j * F4 + c4]);
        acc.x = fmaf(v, b.x, acc.x);
        acc.y = fmaf(v, b.y, acc.y);
        acc.z = fmaf(v, b.z, acc.z);
        acc.w = fmaf(v, b.w, acc.w);
    }
    float4 yn = make_float4(2.0f * acc.x - p.x, 2.0f * acc.y - p.y,
                            2.0f * acc.z - p.z, 2.0f * acc.w - p.w);
    Ynew[o] = yn;

    ov.x = fmaf(ck, yn.x, ov.x);
    ov.y = fmaf(ck, yn.y, ov.y);
    ov.z = fmaf(ck, yn.z, ov.z);
    ov.w = fmaf(ck, yn.w, ov.w);
    reinterpret_cast<float4*>(out)[o] = ov;
}

// ---------------------------------------------------------------------------
extern "C" void kernel_launch(void* const* d_in, const int* in_sizes, int n_in,
                              void* d_out, int out_size) {
    const float* x   = (const float*)d_in[0];   // [N, F]
    const float* P   = (const float*)d_in[1];   // [N, N]
    const float* t   = (const float*)d_in[2];   // [N]
    const float* eig = (const float*)d_in[3];   // [1]
    float* out = (float*)d_out;

    k_prep<<<512, 256>>>(P, t, eig);            // build ELL || coefficients

    int do_tail = (out_size >= N_ * F_ + N_) ? 1 : 0;
    k_first<<<N_ / 2, 256>>>(x, out, t, do_tail);   // y1 = Lx, out = c0 x + c1 y1

    // k=2 uses x as y_prev (ip = -1); buffers rotate over g_Y[0..2]
    int ip = -1, ic = 0, inew = 1;
    for (int k = 2; k <= M_; k++) {
        k_step<<<N_ / 2, 256>>>(x, ip, ic, inew, k, out);
        ip = ic; ic = inew; inew = (inew + 1) % 3;
        if (ip == 0 && ic == 1) inew = 2;       // keep 3-buffer rotation valid
    }
}